// round 14
// baseline (speedup 1.0000x reference)
#include <cuda_runtime.h>
#include <cuda_fp16.h>
#include <math.h>
#include <stdint.h>

// ---------------- problem constants ----------------
#define NB   4
#define TT   2048
#define CEMB 768
#define C3   (3 * CEMB)       // 2304
#define HID  (4 * CEMB)       // 3072
#define NH   12
#define HD   64
#define BT   (NB * TT)        // 8192
#define LNEPS 1e-5f
#define LOG2E 1.4426950408889634f

// GEMM tiling (halves): BK=64, 3 stages, single barrier per slab
#define BK      64
#define KPAD_H  72
#define STG_H   (128 * KPAD_H)         // 9216 halves per operand per stage
#define STAGE_H (2 * STG_H)            // 18432 halves (A+B)
#define GEMM_SMEM (3 * STAGE_H * 2)    // 110592 bytes

// n64 GEMM variant (128x64 CTA tile, 8 warps 4x2, 32x32 warp tile, 2 stages)
#define STGA64_H (128 * KPAD_H)        // 9216
#define STGB64_H (64 * KPAD_H)         // 4608
#define STAGE64_H (STGA64_H + STGB64_H)  // 13824
#define GEMM64_SMEM (2 * STAGE64_H * 2)  // 55296 bytes

// V-stage transpose pad (halves)
#define VSTG_PAD 136

// attention tiling (halves)
#define QT     128
#define KT     64
#define APAD_H 72
#define QS_H   (QT * APAD_H)           // 9216
#define KV_H   (KT * APAD_H)           // 4608
#define ASTG_H (2 * KV_H)              // 9216
#define ATT_SMEM ((QS_H + 3 * ASTG_H) * 2)   // 73728 bytes

// ---------------- scratch ----------------
__device__ __half g_ln [BT * CEMB];
__device__ __half g_qkv[BT * C3];
__device__ __half g_vT [NB * NH * HD * TT];
__device__ __half g_att[BT * CEMB];
__device__ float  g_x1 [BT * CEMB];
__device__ __half g_h  [BT * HID];
__device__ __half g_wattT [C3 * CEMB];
__device__ __half g_woT   [CEMB * CEMB];
__device__ __half g_wfcT  [HID * CEMB];
__device__ __half g_wprojT[CEMB * HID];

// ---------------- helpers ----------------
__device__ __forceinline__ uint32_t smem_u32(const void* p) {
    uint32_t a;
    asm("{ .reg .u64 t; cvta.to.shared.u64 t, %1; cvt.u32.u64 %0, t; }"
        : "=r"(a) : "l"(p));
    return a;
}

__device__ __forceinline__ void cp16(uint32_t sa, const void* ga) {
    asm volatile("cp.async.cg.shared.global [%0], [%1], 16;"
                 :: "r"(sa), "l"(ga));
}

__device__ __forceinline__ void mma_f16(float* d, const uint32_t* a,
                                        const uint32_t* b) {
    asm volatile(
        "mma.sync.aligned.m16n8k16.row.col.f32.f16.f16.f32 "
        "{%0,%1,%2,%3}, {%4,%5,%6,%7}, {%8,%9}, {%0,%1,%2,%3};"
        : "+f"(d[0]), "+f"(d[1]), "+f"(d[2]), "+f"(d[3])
        : "r"(a[0]), "r"(a[1]), "r"(a[2]), "r"(a[3]),
          "r"(b[0]), "r"(b[1]));
}

__device__ __forceinline__ uint32_t packh2(float x, float y) {
    __half2 h = __float22half2_rn(make_float2(x, y));
    return *(uint32_t*)&h;
}

// ---------------- fused prep: 4 weight transposes + ln1 (one launch) -----
#define TR_T0 1728
#define TR_T1 (TR_T0 + 576)    // 2304
#define TR_T2 (TR_T1 + 2304)   // 4608
#define TR_TOTAL (TR_T2 + 2304) // 6912
#define PREP_TOTAL (TR_TOTAL + BT)  // 15104
__global__ __launch_bounds__(256) void prep_kernel(
    const float* __restrict__ W0, const float* __restrict__ W1,
    const float* __restrict__ W2, const float* __restrict__ W3,
    __half* __restrict__ T0, __half* __restrict__ T1,
    __half* __restrict__ T2, __half* __restrict__ T3,
    const float* __restrict__ x, const float* __restrict__ lng,
    const float* __restrict__ lnb, __half* __restrict__ lnout)
{
    int id = blockIdx.x;
    int tid = threadIdx.x;

    if (id >= TR_TOTAL) {
        int row = id - TR_TOTAL;
        const float* xr = x + (size_t)row * CEMB;

        float v[3];
#pragma unroll
        for (int i = 0; i < 3; i++) v[i] = xr[tid + i * 256];

        float s = v[0] + v[1] + v[2];
        float q = v[0] * v[0] + v[1] * v[1] + v[2] * v[2];

        __shared__ float ssum[8], ssq[8];
#pragma unroll
        for (int o = 16; o > 0; o >>= 1) {
            s += __shfl_xor_sync(0xffffffffu, s, o);
            q += __shfl_xor_sync(0xffffffffu, q, o);
        }
        if ((tid & 31) == 0) { ssum[tid >> 5] = s; ssq[tid >> 5] = q; }
        __syncthreads();
        if (tid < 32) {
            s = (tid < 8) ? ssum[tid] : 0.f;
            q = (tid < 8) ? ssq [tid] : 0.f;
#pragma unroll
            for (int o = 4; o > 0; o >>= 1) {
                s += __shfl_xor_sync(0xffffffffu, s, o);
                q += __shfl_xor_sync(0xffffffffu, q, o);
            }
            if (tid == 0) { ssum[0] = s; ssq[0] = q; }
        }
        __syncthreads();

        float mean = ssum[0] * (1.0f / CEMB);
        float var  = ssq[0]  * (1.0f / CEMB) - mean * mean;
        float rstd = rsqrtf(var + LNEPS);

        __half* orow = lnout + (size_t)row * CEMB;
#pragma unroll
        for (int i = 0; i < 3; i++) {
            int c = tid + i * 256;
            orow[c] = __float2half_rn((v[i] - mean) * rstd * lng[c] + lnb[c]);
        }
        return;
    }

    const float* W; __half* WT; int K, N, bx, by, t;
    if (id < TR_T0)       { W = W0; WT = T0; K = CEMB; N = C3;
                            t = id;          bx = t % 72; by = t / 72; }
    else if (id < TR_T1)  { W = W1; WT = T1; K = CEMB; N = CEMB;
                            t = id - TR_T0;  bx = t % 24; by = t / 24; }
    else if (id < TR_T2)  { W = W2; WT = T2; K = CEMB; N = HID;
                            t = id - TR_T1;  bx = t % 96; by = t / 96; }
    else                  { W = W3; WT = T3; K = HID;  N = CEMB;
                            t = id - TR_T2;  bx = t % 24; by = t / 24; }
    bx *= 32; by *= 32;

    __shared__ float tb[32][33];
    int tx = tid & 31, ty = tid >> 5;
#pragma unroll
    for (int i = 0; i < 32; i += 8)
        tb[ty + i][tx] = W[(size_t)(by + ty + i) * N + bx + tx];
    __syncthreads();
#pragma unroll
    for (int i = 0; i < 32; i += 8)
        WT[(size_t)(bx + ty + i) * K + by + tx] = __float2half_rn(tb[tx][ty + i]);
}

// ---------------- layernorm (fp32 in, fp16 out) ----------------
__global__ __launch_bounds__(256) void ln_kernel(
    const float* __restrict__ x, const float* __restrict__ g,
    const float* __restrict__ b, __half* __restrict__ out)
{
    int row = blockIdx.x;
    int tid = threadIdx.x;
    const float* xr = x + (size_t)row * CEMB;

    float v[3];
#pragma unroll
    for (int i = 0; i < 3; i++) v[i] = xr[tid + i * 256];

    float s = v[0] + v[1] + v[2];
    float q = v[0] * v[0] + v[1] * v[1] + v[2] * v[2];

    __shared__ float ssum[8], ssq[8];
#pragma unroll
    for (int o = 16; o > 0; o >>= 1) {
        s += __shfl_xor_sync(0xffffffffu, s, o);
        q += __shfl_xor_sync(0xffffffffu, q, o);
    }
    if ((tid & 31) == 0) { ssum[tid >> 5] = s; ssq[tid >> 5] = q; }
    __syncthreads();
    if (tid < 32) {
        s = (tid < 8) ? ssum[tid] : 0.f;
        q = (tid < 8) ? ssq [tid] : 0.f;
#pragma unroll
        for (int o = 4; o > 0; o >>= 1) {
            s += __shfl_xor_sync(0xffffffffu, s, o);
            q += __shfl_xor_sync(0xffffffffu, q, o);
        }
        if (tid == 0) { ssum[0] = s; ssq[0] = q; }
    }
    __syncthreads();

    float mean = ssum[0] * (1.0f / CEMB);
    float var  = ssq[0]  * (1.0f / CEMB) - mean * mean;
    float rstd = rsqrtf(var + LNEPS);

    __half* orow = out + (size_t)row * CEMB;
#pragma unroll
    for (int i = 0; i < 3; i++) {
        int c = tid + i * 256;
        orow[c] = __float2half_rn((v[i] - mean) * rstd * g[c] + b[c]);
    }
}

// ---------------- mma.sync fp16 GEMM: C = A[M,K] @ Bt[N,K]^T (+epi) ------
// EPI: 1 -> float out + residual R, 2 -> gelu + half out,
//      4 -> qkv mode: QK cols to C; V tiles staged in smem, coalesced to vTp
template <int EPI>
__global__ __launch_bounds__(256) void mma_gemm(
    const __half* __restrict__ A, const __half* __restrict__ Bt,
    const float* __restrict__ R, void* __restrict__ Cv,
    __half* __restrict__ vTp,
    int M, int N, int K)
{
    extern __shared__ __half smh[];

    int tid  = threadIdx.x;
    int wid  = tid >> 5;
    int lane = tid & 31;
    int gid  = lane >> 2;
    int tig  = lane & 3;

    int m0 = blockIdx.y * 128, n0 = blockIdx.x * 128;
    int wm = (wid >> 2) * 64;
    int wn = (wid & 3) * 32;

    uint32_t su = smem_u32(smh);

    float acc[4][4][4];
#pragma unroll
    for (int mi = 0; mi < 4; mi++)
#pragma unroll
        for (int ni = 0; ni < 4; ni++)
#pragma unroll
            for (int r = 0; r < 4; r++) acc[mi][ni][r] = 0.f;

    const int KS = K / BK;

#define LOAD_SLAB(i) do {                                                   \
    int _k0 = (i) * BK;                                                     \
    uint32_t base = su + (uint32_t)((i) % 3) * (STAGE_H * 2);               \
    _Pragma("unroll")                                                       \
    for (int it = 0; it < 4; it++) {                                        \
        int idx = it * 256 + tid;                                           \
        int r = idx >> 3, c = idx & 7;                                      \
        uint32_t off = (uint32_t)r * (KPAD_H * 2) + (uint32_t)c * 16;       \
        cp16(base + off,                                                    \
             A  + (size_t)(m0 + r) * K + _k0 + c * 8);                      \
        cp16(base + (STG_H * 2) + off,                                      \
             Bt + (size_t)(n0 + r) * K + _k0 + c * 8);                      \
    }                                                                       \
    asm volatile("cp.async.commit_group;" ::: "memory");                    \
} while (0)

    LOAD_SLAB(0);
    LOAD_SLAB(1);

    for (int i = 0; i < KS; i++) {
        if (i + 1 < KS) {
            asm volatile("cp.async.wait_group 1;" ::: "memory");
        } else {
            asm volatile("cp.async.wait_group 0;" ::: "memory");
        }
        __syncthreads();
        if (i + 2 < KS) LOAD_SLAB(i + 2);

        const __half* As = smh + (i % 3) * STAGE_H;
        const __half* Bs = As + STG_H;

#pragma unroll
        for (int kk = 0; kk < 4; kk++) {
            int kb = kk * 16;
            uint32_t a[4][4], b[4][2];
#pragma unroll
            for (int mi = 0; mi < 4; mi++) {
                int r0 = wm + mi * 16 + gid;
                a[mi][0] = *(const uint32_t*)&As[(r0    ) * KPAD_H + kb + 2 * tig    ];
                a[mi][1] = *(const uint32_t*)&As[(r0 + 8) * KPAD_H + kb + 2 * tig    ];
                a[mi][2] = *(const uint32_t*)&As[(r0    ) * KPAD_H + kb + 2 * tig + 8];
                a[mi][3] = *(const uint32_t*)&As[(r0 + 8) * KPAD_H + kb + 2 * tig + 8];
            }
#pragma unroll
            for (int ni = 0; ni < 4; ni++) {
                int c0 = wn + ni * 8 + gid;
                b[ni][0] = *(const uint32_t*)&Bs[c0 * KPAD_H + kb + 2 * tig    ];
                b[ni][1] = *(const uint32_t*)&Bs[c0 * KPAD_H + kb + 2 * tig + 8];
            }
#pragma unroll
            for (int mi = 0; mi < 4; mi++)
#pragma unroll
                for (int ni = 0; ni < 4; ni++)
                    mma_f16(acc[mi][ni], a[mi], b[ni]);
        }
    }

    // ---- epilogue ----
    if (EPI == 4 && n0 >= 2 * CEMB) {
        __syncthreads();
#pragma unroll
        for (int mi = 0; mi < 4; mi++) {
#pragma unroll
            for (int half_ = 0; half_ < 2; half_++) {
                int lrow = wm + mi * 16 + gid + half_ * 8;
#pragma unroll
                for (int ni = 0; ni < 4; ni++) {
                    int lcol = wn + ni * 8 + tig * 2;
                    float vx = acc[mi][ni][half_ * 2 + 0];
                    float vy = acc[mi][ni][half_ * 2 + 1];
                    smh[(lcol    ) * VSTG_PAD + lrow] = __float2half_rn(vx);
                    smh[(lcol + 1) * VSTG_PAD + lrow] = __float2half_rn(vy);
                }
            }
        }
        __syncthreads();

        int b_ = m0 / TT;
        int t_base = m0 % TT;
        int cc0 = n0 - 2 * CEMB;
#pragma unroll
        for (int it = 0; it < 8; it++) {
            int idx = it * 256 + tid;
            int l  = idx >> 4;
            int ch = idx & 15;
            int gcol = cc0 + l;
            __half* dst = vTp +
                ((size_t)(b_ * NH + (gcol >> 6)) * HD + (gcol & 63)) * TT
                + t_base + ch * 8;
            *(float4*)dst = *(const float4*)&smh[l * VSTG_PAD + ch * 8];
        }
        return;
    }

#pragma unroll
    for (int mi = 0; mi < 4; mi++) {
        int row0 = m0 + wm + mi * 16 + gid;
#pragma unroll
        for (int half_ = 0; half_ < 2; half_++) {
            int row = row0 + half_ * 8;
#pragma unroll
            for (int ni = 0; ni < 4; ni++) {
                int col = n0 + wn + ni * 8 + tig * 2;
                float vx = acc[mi][ni][half_ * 2 + 0];
                float vy = acc[mi][ni][half_ * 2 + 1];
                if (EPI == 1) {
                    float* C = (float*)Cv;
                    float2 rr = *(const float2*)&R[(size_t)row * N + col];
                    float2 v; v.x = vx + rr.x; v.y = vy + rr.y;
                    *(float2*)&C[(size_t)row * N + col] = v;
                } else {
                    if (EPI == 2) {
                        vx = 0.5f * vx * (1.0f + erff(vx * 0.70710678118654752f));
                        vy = 0.5f * vy * (1.0f + erff(vy * 0.70710678118654752f));
                    }
                    __half* C = (__half*)Cv;
                    *(uint32_t*)&C[(size_t)row * N + col] = packh2(vx, vy);
                }
            }
        }
    }
#undef LOAD_SLAB
}

// ---------------- n64 v2: 128x64 CTA tile, 8 warps (4x2), 32x32 warp tile
// 256 threads, 2 stages; float out + residual. 4 CTAs/SM target.
__global__ __launch_bounds__(256) void mma_gemm_n64(
    const __half* __restrict__ A, const __half* __restrict__ Bt,
    const float* __restrict__ R, float* __restrict__ C,
    int M, int N, int K)
{
    extern __shared__ __half smh[];

    int tid  = threadIdx.x;
    int wid  = tid >> 5;
    int lane = tid & 31;
    int gid  = lane >> 2;
    int tig  = lane & 3;

    int m0 = blockIdx.y * 128, n0 = blockIdx.x * 64;
    int wm = (wid >> 1) * 32;     // 0/32/64/96
    int wn = (wid & 1) * 32;      // 0/32

    uint32_t su = smem_u32(smh);

    float acc[2][4][4];
#pragma unroll
    for (int mi = 0; mi < 2; mi++)
#pragma unroll
        for (int ni = 0; ni < 4; ni++)
#pragma unroll
            for (int r = 0; r < 4; r++) acc[mi][ni][r] = 0.f;

    const int KS = K / BK;

#define LOAD_SLAB64(i) do {                                                 \
    int _k0 = (i) * BK;                                                     \
    uint32_t base = su + (uint32_t)((i) & 1) * (STAGE64_H * 2);             \
    _Pragma("unroll")                                                       \
    for (int it = 0; it < 4; it++) {                                        \
        int idx = it * 256 + tid;                                           \
        int r = idx >> 3, c = idx & 7;                                      \
        cp16(base + (uint32_t)r * (KPAD_H * 2) + (uint32_t)c * 16,          \
             A + (size_t)(m0 + r) * K + _k0 + c * 8);                       \
    }                                                                       \
    _Pragma("unroll")                                                       \
    for (int it = 0; it < 2; it++) {                                        \
        int idx = it * 256 + tid;                                           \
        int r = idx >> 3, c = idx & 7;                                      \
        cp16(base + (STGA64_H * 2) + (uint32_t)r * (KPAD_H * 2)             \
             + (uint32_t)c * 16,                                            \
             Bt + (size_t)(n0 + r) * K + _k0 + c * 8);                      \
    }                                                                       \
    asm volatile("cp.async.commit_group;" ::: "memory");                    \
} while (0)

    LOAD_SLAB64(0);

    for (int i = 0; i < KS; i++) {
        if (i + 1 < KS) {
            LOAD_SLAB64(i + 1);
            asm volatile("cp.async.wait_group 1;" ::: "memory");
        } else {
            asm volatile("cp.async.wait_group 0;" ::: "memory");
        }
        __syncthreads();

        const __half* As = smh + (i & 1) * STAGE64_H;
        const __half* Bs = As + STGA64_H;

#pragma unroll
        for (int kk = 0; kk < 4; kk++) {
            int kb = kk * 16;
            uint32_t a[2][4], b[4][2];
#pragma unroll
            for (int mi = 0; mi < 2; mi++) {
                int r0 = wm + mi * 16 + gid;
                a[mi][0] = *(const uint32_t*)&As[(r0    ) * KPAD_H + kb + 2 * tig    ];
                a[mi][1] = *(const uint32_t*)&As[(r0 + 8) * KPAD_H + kb + 2 * tig    ];
                a[mi][2] = *(const uint32_t*)&As[(r0    ) * KPAD_H + kb + 2 * tig + 8];
                a[mi][3] = *(const uint32_t*)&As[(r0 + 8) * KPAD_H + kb + 2 * tig + 8];
            }
#pragma unroll
            for (int ni = 0; ni < 4; ni++) {
                int c0 = wn + ni * 8 + gid;
                b[ni][0] = *(const uint32_t*)&Bs[c0 * KPAD_H + kb + 2 * tig    ];
                b[ni][1] = *(const uint32_t*)&Bs[c0 * KPAD_H + kb + 2 * tig + 8];
            }
#pragma unroll
            for (int mi = 0; mi < 2; mi++)
#pragma unroll
                for (int ni = 0; ni < 4; ni++)
                    mma_f16(acc[mi][ni], a[mi], b[ni]);
        }
        __syncthreads();
    }

#pragma unroll
    for (int mi = 0; mi < 2; mi++) {
        int row0 = m0 + wm + mi * 16 + gid;
#pragma unroll
        for (int half_ = 0; half_ < 2; half_++) {
            int row = row0 + half_ * 8;
#pragma unroll
            for (int ni = 0; ni < 4; ni++) {
                int col = n0 + wn + ni * 8 + tig * 2;
                float vx = acc[mi][ni][half_ * 2 + 0];
                float vy = acc[mi][ni][half_ * 2 + 1];
                float2 rr = *(const float2*)&R[(size_t)row * N + col];
                float2 v; v.x = vx + rr.x; v.y = vy + rr.y;
                *(float2*)&C[(size_t)row * N + col] = v;
            }
        }
    }
#undef LOAD_SLAB64
}

// ---------------- MMA flash attention (causal, fp16) — R11 config --------
__global__ __launch_bounds__(256) void attn_mma(
    const __half* __restrict__ qkv, const __half* __restrict__ vT,
    __half* __restrict__ y)
{
    extern __shared__ __half smh[];
    int tid  = threadIdx.x;
    int wid  = tid >> 5;
    int lane = tid & 31;
    int gid  = lane >> 2;
    int tig  = lane & 3;

    int qt = blockIdx.x;
    int h = blockIdx.y, b = blockIdx.z;
    int q0 = qt * QT;
    int ntiles = 2 * qt + 2;

    const __half* qbase = qkv + (size_t)b * TT * C3 + h * HD;
    const __half* kbase = qkv + (size_t)b * TT * C3 + CEMB + h * HD;
    const __half* vbase = vT + (size_t)(b * NH + h) * HD * TT;

    uint32_t su = smem_u32(smh);

#pragma unroll
    for (int it = 0; it < 4; it++) {
        int idx = it * 256 + tid;
        int r = idx >> 3, c = idx & 7;
        cp16(su + (uint32_t)(r * APAD_H + c * 8) * 2,
             qbase + (size_t)(q0 + r) * C3 + c * 8);
    }

#define LOAD_KV(k0, s) do {                                                  \
    uint32_t kdst = su + (uint32_t)(QS_H + (s) * ASTG_H) * 2;                \
    uint32_t vdst = kdst + KV_H * 2;                                         \
    _Pragma("unroll")                                                        \
    for (int it = 0; it < 2; it++) {                                         \
        int idx = it * 256 + tid;                                            \
        int r = idx >> 3, c = idx & 7;                                       \
        uint32_t off = (uint32_t)(r * APAD_H + c * 8) * 2;                   \
        cp16(kdst + off, kbase + (size_t)((k0) + r) * C3 + c * 8);           \
        cp16(vdst + off, vbase + (size_t)r * TT + (k0) + c * 8);             \
    }                                                                        \
    asm volatile("cp.async.commit_group;" ::: "memory");                     \
} while (0)

    LOAD_KV(0, 0);
    LOAD_KV(KT, 1);

    uint32_t qf[4][4];
    float o[8][4];
#pragma unroll
    for (int ni = 0; ni < 8; ni++)
#pragma unroll
        for (int r = 0; r < 4; r++) o[ni][r] = 0.f;
    float m0v = -INFINITY, m1v = -INFINITY, l0 = 0.f, l1 = 0.f;

    int rw = wid * 16 + gid;
    const __half2 hscale = __float2half2_rn(0.125f);

    for (int i = 0; i < ntiles; i++) {
        if (i < ntiles - 1) {
            asm volatile("cp.async.wait_group 1;" ::: "memory");
        } else {
            asm volatile("cp.async.wait_group 0;" ::: "memory");
        }
        __syncthreads();

        if (i + 2 < ntiles) LOAD_KV((i + 2) * KT, (i + 2) % 3);

        if (i == 0) {
#pragma unroll
            for (int kk = 0; kk < 4; kk++) {
                int kb = kk * 16;
                __half2 h0 = __hmul2(*(const __half2*)&smh[(rw    ) * APAD_H + kb + 2 * tig    ], hscale);
                __half2 h1 = __hmul2(*(const __half2*)&smh[(rw + 8) * APAD_H + kb + 2 * tig    ], hscale);
                __half2 h2 = __hmul2(*(const __half2*)&smh[(rw    ) * APAD_H + kb + 2 * tig + 8], hscale);
                __half2 h3 = __hmul2(*(const __half2*)&smh[(rw + 8) * APAD_H + kb + 2 * tig + 8], hscale);
                qf[kk][0] = *(uint32_t*)&h0; qf[kk][1] = *(uint32_t*)&h1;
                qf[kk][2] = *(uint32_t*)&h2; qf[kk][3] = *(uint32_t*)&h3;
            }
        }

        int k0 = i * KT;
        bool active = (q0 + wid * 16 + 15) >= k0;
        if (active) {
            const __half* Ks = smh + QS_H + (i % 3) * ASTG_H;
            const __half* Vs = Ks + KV_H;

            float sacc[8][4];
#pragma unroll
            for (int ni = 0; ni < 8; ni++)
#pragma unroll
                for (int r = 0; r < 4; r++) sacc[ni][r] = 0.f;

#pragma unroll
            for (int kk = 0; kk < 4; kk++) {
                int kb = kk * 16;
#pragma unroll
                for (int ni = 0; ni < 8; ni++) {
                    uint32_t bb[2];
                    bb[0] = *(const uint32_t*)&Ks[(ni * 8 + gid) * APAD_H + kb + 2 * tig    ];
                    bb[1] = *(const uint32_t*)&Ks[(ni * 8 + gid) * APAD_H + kb + 2 * tig + 8];
                    mma_f16(sacc[ni], qf[kk], bb);
                }
            }

            if (i >= ntiles - 2) {
                int row0 = q0 + rw;
#pragma unroll
                for (int ni = 0; ni < 8; ni++) {
#pragma unroll
                    for (int r = 0; r < 4; r++) {
                        int col = k0 + ni * 8 + 2 * tig + (r & 1);
                        int row = row0 + ((r >= 2) ? 8 : 0);
                        if (col > row) sacc[ni][r] = -INFINITY;
                    }
                }
            }

            float t0 = -INFINITY, t1 = -INFINITY;
#pragma unroll
            for (int ni = 0; ni < 8; ni++) {
                t0 = fmaxf(t0, fmaxf(sacc[ni][0], sacc[ni][1]));
                t1 = fmaxf(t1, fmaxf(sacc[ni][2], sacc[ni][3]));
            }
            t0 = fmaxf(t0, __shfl_xor_sync(0xffffffffu, t0, 1));
            t0 = fmaxf(t0, __shfl_xor_sync(0xffffffffu, t0, 2));
            t1 = fmaxf(t1, __shfl_xor_sync(0xffffffffu, t1, 1));
            t1 = fmaxf(t1, __shfl_xor_sync(0xffffffffu, t1, 2));

            float mn0 = fmaxf(m0v, t0), mn1 = fmaxf(m1v, t1);
            float al0 = exp2f((m0v - mn0) * LOG2E);
            float al1 = exp2f((m1v - mn1) * LOG2E);
            m0v = mn0; m1v = mn1;
            l0 *= al0;  l1 *= al1;
#pragma unroll
            for (int ni = 0; ni < 8; ni++) {
                o[ni][0] *= al0; o[ni][1] *= al0;
                o[ni][2] *= al1; o[ni][3] *= al1;
            }

            uint32_t pf[4][4];
#pragma unroll
            for (int kk = 0; kk < 4; kk++) {
                float p00 = exp2f((sacc[2 * kk    ][0] - mn0) * LOG2E);
                float p01 = exp2f((sacc[2 * kk    ][1] - mn0) * LOG2E);
                float p02 = exp2f((sacc[2 * kk    ][2] - mn1) * LOG2E);
                float p03 = exp2f((sacc[2 * kk    ][3] - mn1) * LOG2E);
                float p10 = exp2f((sacc[2 * kk + 1][0] - mn0) * LOG2E);
                float p11 = exp2f((sacc[2 * kk + 1][1] - mn0) * LOG2E);
                float p12 = exp2f((sacc[2 * kk + 1][2] - mn1) * LOG2E);
                float p13 = exp2f((sacc[2 * kk + 1][3] - mn1) * LOG2E);
                l0 += p00 + p01 + p10 + p11;
                l1 += p02 + p03 + p12 + p13;
                pf[kk][0] = packh2(p00, p01);
                pf[kk][1] = packh2(p02, p03);
                pf[kk][2] = packh2(p10, p11);
                pf[kk][3] = packh2(p12, p13);
            }

#pragma unroll
            for (int kk = 0; kk < 4; kk++) {
                int kb = kk * 16;
#pragma unroll
                for (int ni = 0; ni < 8; ni++) {
                    uint32_t bb[2];
                    bb[0] = *(const uint32_t*)&Vs[(ni * 8 + gid) * APAD_H + kb + 2 * tig    ];
                    bb[1] = *(const uint32_t*)&Vs[(ni * 8 + gid) * APAD_H + kb + 2 * tig + 8];
                    mma_f16(o[ni], pf[kk], bb);
                }
            }
        }
        __syncthreads();
    }

    l0 += __shfl_xor_sync(0xffffffffu, l0, 1);
    l0 += __shfl_xor_sync(0xffffffffu, l0, 2);
    l1 += __shfl_xor_sync(0xffffffffu, l1, 1);
    l1 += __shfl_xor_sync(0xffffffffu, l1, 2);
    float r0 = 1.0f / l0, r1 = 1.0f / l1;

    int grow0 = (b * TT + q0 + rw);
#pragma unroll
    for (int ni = 0; ni < 8; ni++) {
        int col = h * HD + ni * 8 + 2 * tig;
        *(uint32_t*)&y[(size_t)grow0 * CEMB + col]       = packh2(o[ni][0] * r0, o[ni][1] * r0);
        *(uint32_t*)&y[(size_t)(grow0 + 8) * CEMB + col] = packh2(o[ni][2] * r1, o[ni][3] * r1);
    }
#undef LOAD_KV
}

// ---------------- launch ----------------
extern "C" void kernel_launch(void* const* d_in, const int* in_sizes, int n_in,
                              void* d_out, int out_size)
{
    (void)in_sizes; (void)n_in; (void)out_size;
    const float* x      = (const float*)d_in[0];
    const float* ln1_g  = (const float*)d_in[1];
    const float* ln1_b  = (const float*)d_in[2];
    const float* W_attn = (const float*)d_in[3];
    const float* W_o    = (const float*)d_in[4];
    const float* ln2_g  = (const float*)d_in[5];
    const float* ln2_b  = (const float*)d_in[6];
    const float* W_fc   = (const float*)d_in[7];
    const float* W_proj = (const float*)d_in[8];
    float* out = (float*)d_out;

    __half *p_ln, *p_qkv, *p_vT, *p_att, *p_h;
    __half *p_wattT, *p_woT, *p_wfcT, *p_wprojT;
    float *p_x1;
    cudaGetSymbolAddress((void**)&p_ln,     g_ln);
    cudaGetSymbolAddress((void**)&p_qkv,    g_qkv);
    cudaGetSymbolAddress((void**)&p_vT,     g_vT);
    cudaGetSymbolAddress((void**)&p_att,    g_att);
    cudaGetSymbolAddress((void**)&p_x1,     g_x1);
    cudaGetSymbolAddress((void**)&p_h,      g_h);
    cudaGetSymbolAddress((void**)&p_wattT,  g_wattT);
    cudaGetSymbolAddress((void**)&p_woT,    g_woT);
    cudaGetSymbolAddress((void**)&p_wfcT,   g_wfcT);
    cudaGetSymbolAddress((void**)&p_wprojT, g_wprojT);

    cudaFuncSetAttribute(mma_gemm<2>, cudaFuncAttributeMaxDynamicSharedMemorySize, GEMM_SMEM);
    cudaFuncSetAttribute(mma_gemm<4>, cudaFuncAttributeMaxDynamicSharedMemorySize, GEMM_SMEM);
    cudaFuncSetAttribute(mma_gemm_n64, cudaFuncAttributeMaxDynamicSharedMemorySize, GEMM64_SMEM);
    cudaFuncSetAttribute(attn_mma, cudaFuncAttributeMaxDynamicSharedMemorySize, ATT_SMEM);

    // 0. fused prep: all weight transposes + ln1 in one launch
    prep_kernel<<<PREP_TOTAL, 256>>>(W_attn, W_o, W_fc, W_proj,
                                     p_wattT, p_woT, p_wfcT, p_wprojT,
                                     x, ln1_g, ln1_b, p_ln);

    // 2. qkv = ln1 @ W_attn; Q,K to g_qkv, V staged+transposed to g_vT
    mma_gemm<4><<<dim3(C3 / 128, BT / 128), 256, GEMM_SMEM>>>(
        p_ln, p_wattT, nullptr, p_qkv, p_vT, BT, C3, CEMB);

    // 3. MMA flash attention (half out)
    attn_mma<<<dim3(TT / QT, NH, NB), 256, ATT_SMEM>>>(p_qkv, p_vT, p_att);

    // 4. x1 = att @ W_o + x (float out, n64 v2)
    mma_gemm_n64<<<dim3(CEMB / 64, BT / 128), 256, GEMM64_SMEM>>>(
        p_att, p_woT, x, p_x1, BT, CEMB, CEMB);

    // 5. ln2
    ln_kernel<<<BT, 256>>>(p_x1, ln2_g, ln2_b, p_ln);

    // 6. h = gelu(ln2 @ W_fc) (half out)
    mma_gemm<2><<<dim3(HID / 128, BT / 128), 256, GEMM_SMEM>>>(
        p_ln, p_wfcT, nullptr, p_h, nullptr, BT, HID, CEMB);

    // 7. out = h @ W_proj + x1 (float out, n64 v2)
    mma_gemm_n64<<<dim3(CEMB / 64, BT / 128), 256, GEMM64_SMEM>>>(
        p_h, p_wprojT, p_x1, out, BT, CEMB, HID);
}

// round 15
// speedup vs baseline: 1.0371x; 1.0371x over previous
#include <cuda_runtime.h>
#include <cuda_fp16.h>
#include <math.h>
#include <stdint.h>

// ---------------- problem constants ----------------
#define NB   4
#define TT   2048
#define CEMB 768
#define C3   (3 * CEMB)       // 2304
#define HID  (4 * CEMB)       // 3072
#define NH   12
#define HD   64
#define BT   (NB * TT)        // 8192
#define LNEPS 1e-5f
#define LOG2E 1.4426950408889634f

// GEMM tiling (halves): BK=64, 3 stages, single barrier per slab
#define BK      64
#define KPAD_H  72
#define STG_H   (128 * KPAD_H)         // 9216 halves per operand per stage
#define STAGE_H (2 * STG_H)            // 18432 halves (A+B)
#define GEMM_SMEM (3 * STAGE_H * 2)    // 110592 bytes

// n64 GEMM variant v1 (128x64 CTA tile, 4 warps, 64x32 warp tile, 2 stages)
#define STGA64_H (128 * KPAD_H)        // 9216
#define STGB64_H (64 * KPAD_H)         // 4608
#define STAGE64_H (STGA64_H + STGB64_H)  // 13824
#define GEMM64_SMEM (2 * STAGE64_H * 2)  // 55296 bytes

// V-stage transpose pad (halves)
#define VSTG_PAD 136

// attention tiling (halves)
#define QT     128
#define KT     64
#define APAD_H 72
#define QS_H   (QT * APAD_H)           // 9216
#define KV_H   (KT * APAD_H)           // 4608
#define ASTG_H (2 * KV_H)              // 9216
#define ATT_SMEM ((QS_H + 3 * ASTG_H) * 2)   // 73728 bytes

// ---------------- scratch ----------------
__device__ __half g_ln [BT * CEMB];
__device__ __half g_qkv[BT * C3];
__device__ __half g_vT [NB * NH * HD * TT];
__device__ __half g_att[BT * CEMB];
__device__ float  g_x1 [BT * CEMB];
__device__ __half g_h  [BT * HID];
__device__ __half g_wattT [C3 * CEMB];
__device__ __half g_woT   [CEMB * CEMB];
__device__ __half g_wfcT  [HID * CEMB];
__device__ __half g_wprojT[CEMB * HID];

// ---------------- helpers ----------------
__device__ __forceinline__ uint32_t smem_u32(const void* p) {
    uint32_t a;
    asm("{ .reg .u64 t; cvta.to.shared.u64 t, %1; cvt.u32.u64 %0, t; }"
        : "=r"(a) : "l"(p));
    return a;
}

__device__ __forceinline__ void cp16(uint32_t sa, const void* ga) {
    asm volatile("cp.async.cg.shared.global [%0], [%1], 16;"
                 :: "r"(sa), "l"(ga));
}

__device__ __forceinline__ void mma_f16(float* d, const uint32_t* a,
                                        const uint32_t* b) {
    asm volatile(
        "mma.sync.aligned.m16n8k16.row.col.f32.f16.f16.f32 "
        "{%0,%1,%2,%3}, {%4,%5,%6,%7}, {%8,%9}, {%0,%1,%2,%3};"
        : "+f"(d[0]), "+f"(d[1]), "+f"(d[2]), "+f"(d[3])
        : "r"(a[0]), "r"(a[1]), "r"(a[2]), "r"(a[3]),
          "r"(b[0]), "r"(b[1]));
}

__device__ __forceinline__ uint32_t packh2(float x, float y) {
    __half2 h = __float22half2_rn(make_float2(x, y));
    return *(uint32_t*)&h;
}

// ---------------- fused prep: 4 weight transposes + ln1 (one launch) -----
#define TR_T0 1728
#define TR_T1 (TR_T0 + 576)    // 2304
#define TR_T2 (TR_T1 + 2304)   // 4608
#define TR_TOTAL (TR_T2 + 2304) // 6912
#define PREP_TOTAL (TR_TOTAL + BT)  // 15104
__global__ __launch_bounds__(256) void prep_kernel(
    const float* __restrict__ W0, const float* __restrict__ W1,
    const float* __restrict__ W2, const float* __restrict__ W3,
    __half* __restrict__ T0, __half* __restrict__ T1,
    __half* __restrict__ T2, __half* __restrict__ T3,
    const float* __restrict__ x, const float* __restrict__ lng,
    const float* __restrict__ lnb, __half* __restrict__ lnout)
{
    int id = blockIdx.x;
    int tid = threadIdx.x;

    if (id >= TR_TOTAL) {
        int row = id - TR_TOTAL;
        const float* xr = x + (size_t)row * CEMB;

        float v[3];
#pragma unroll
        for (int i = 0; i < 3; i++) v[i] = xr[tid + i * 256];

        float s = v[0] + v[1] + v[2];
        float q = v[0] * v[0] + v[1] * v[1] + v[2] * v[2];

        __shared__ float ssum[8], ssq[8];
#pragma unroll
        for (int o = 16; o > 0; o >>= 1) {
            s += __shfl_xor_sync(0xffffffffu, s, o);
            q += __shfl_xor_sync(0xffffffffu, q, o);
        }
        if ((tid & 31) == 0) { ssum[tid >> 5] = s; ssq[tid >> 5] = q; }
        __syncthreads();
        if (tid < 32) {
            s = (tid < 8) ? ssum[tid] : 0.f;
            q = (tid < 8) ? ssq [tid] : 0.f;
#pragma unroll
            for (int o = 4; o > 0; o >>= 1) {
                s += __shfl_xor_sync(0xffffffffu, s, o);
                q += __shfl_xor_sync(0xffffffffu, q, o);
            }
            if (tid == 0) { ssum[0] = s; ssq[0] = q; }
        }
        __syncthreads();

        float mean = ssum[0] * (1.0f / CEMB);
        float var  = ssq[0]  * (1.0f / CEMB) - mean * mean;
        float rstd = rsqrtf(var + LNEPS);

        __half* orow = lnout + (size_t)row * CEMB;
#pragma unroll
        for (int i = 0; i < 3; i++) {
            int c = tid + i * 256;
            orow[c] = __float2half_rn((v[i] - mean) * rstd * lng[c] + lnb[c]);
        }
        return;
    }

    const float* W; __half* WT; int K, N, bx, by, t;
    if (id < TR_T0)       { W = W0; WT = T0; K = CEMB; N = C3;
                            t = id;          bx = t % 72; by = t / 72; }
    else if (id < TR_T1)  { W = W1; WT = T1; K = CEMB; N = CEMB;
                            t = id - TR_T0;  bx = t % 24; by = t / 24; }
    else if (id < TR_T2)  { W = W2; WT = T2; K = CEMB; N = HID;
                            t = id - TR_T1;  bx = t % 96; by = t / 96; }
    else                  { W = W3; WT = T3; K = HID;  N = CEMB;
                            t = id - TR_T2;  bx = t % 24; by = t / 24; }
    bx *= 32; by *= 32;

    __shared__ float tb[32][33];
    int tx = tid & 31, ty = tid >> 5;
#pragma unroll
    for (int i = 0; i < 32; i += 8)
        tb[ty + i][tx] = W[(size_t)(by + ty + i) * N + bx + tx];
    __syncthreads();
#pragma unroll
    for (int i = 0; i < 32; i += 8)
        WT[(size_t)(bx + ty + i) * K + by + tx] = __float2half_rn(tb[tx][ty + i]);
}

// ---------------- layernorm (fp32 in, fp16 out) ----------------
__global__ __launch_bounds__(256) void ln_kernel(
    const float* __restrict__ x, const float* __restrict__ g,
    const float* __restrict__ b, __half* __restrict__ out)
{
    int row = blockIdx.x;
    int tid = threadIdx.x;
    const float* xr = x + (size_t)row * CEMB;

    float v[3];
#pragma unroll
    for (int i = 0; i < 3; i++) v[i] = xr[tid + i * 256];

    float s = v[0] + v[1] + v[2];
    float q = v[0] * v[0] + v[1] * v[1] + v[2] * v[2];

    __shared__ float ssum[8], ssq[8];
#pragma unroll
    for (int o = 16; o > 0; o >>= 1) {
        s += __shfl_xor_sync(0xffffffffu, s, o);
        q += __shfl_xor_sync(0xffffffffu, q, o);
    }
    if ((tid & 31) == 0) { ssum[tid >> 5] = s; ssq[tid >> 5] = q; }
    __syncthreads();
    if (tid < 32) {
        s = (tid < 8) ? ssum[tid] : 0.f;
        q = (tid < 8) ? ssq [tid] : 0.f;
#pragma unroll
        for (int o = 4; o > 0; o >>= 1) {
            s += __shfl_xor_sync(0xffffffffu, s, o);
            q += __shfl_xor_sync(0xffffffffu, q, o);
        }
        if (tid == 0) { ssum[0] = s; ssq[0] = q; }
    }
    __syncthreads();

    float mean = ssum[0] * (1.0f / CEMB);
    float var  = ssq[0]  * (1.0f / CEMB) - mean * mean;
    float rstd = rsqrtf(var + LNEPS);

    __half* orow = out + (size_t)row * CEMB;
#pragma unroll
    for (int i = 0; i < 3; i++) {
        int c = tid + i * 256;
        orow[c] = __float2half_rn((v[i] - mean) * rstd * g[c] + b[c]);
    }
}

// ---------------- mma.sync fp16 GEMM: C = A[M,K] @ Bt[N,K]^T (+epi) ------
// EPI: 1 -> float out + residual R, 2 -> gelu + half out,
//      4 -> qkv mode: QK cols to C; V tiles staged in smem, coalesced to vTp
template <int EPI>
__global__ __launch_bounds__(256) void mma_gemm(
    const __half* __restrict__ A, const __half* __restrict__ Bt,
    const float* __restrict__ R, void* __restrict__ Cv,
    __half* __restrict__ vTp,
    int M, int N, int K)
{
    extern __shared__ __half smh[];

    int tid  = threadIdx.x;
    int wid  = tid >> 5;
    int lane = tid & 31;
    int gid  = lane >> 2;
    int tig  = lane & 3;

    int m0 = blockIdx.y * 128, n0 = blockIdx.x * 128;
    int wm = (wid >> 2) * 64;
    int wn = (wid & 3) * 32;

    uint32_t su = smem_u32(smh);

    float acc[4][4][4];
#pragma unroll
    for (int mi = 0; mi < 4; mi++)
#pragma unroll
        for (int ni = 0; ni < 4; ni++)
#pragma unroll
            for (int r = 0; r < 4; r++) acc[mi][ni][r] = 0.f;

    const int KS = K / BK;

#define LOAD_SLAB(i) do {                                                   \
    int _k0 = (i) * BK;                                                     \
    uint32_t base = su + (uint32_t)((i) % 3) * (STAGE_H * 2);               \
    _Pragma("unroll")                                                       \
    for (int it = 0; it < 4; it++) {                                        \
        int idx = it * 256 + tid;                                           \
        int r = idx >> 3, c = idx & 7;                                      \
        uint32_t off = (uint32_t)r * (KPAD_H * 2) + (uint32_t)c * 16;       \
        cp16(base + off,                                                    \
             A  + (size_t)(m0 + r) * K + _k0 + c * 8);                      \
        cp16(base + (STG_H * 2) + off,                                      \
             Bt + (size_t)(n0 + r) * K + _k0 + c * 8);                      \
    }                                                                       \
    asm volatile("cp.async.commit_group;" ::: "memory");                    \
} while (0)

    LOAD_SLAB(0);
    LOAD_SLAB(1);

    for (int i = 0; i < KS; i++) {
        if (i + 1 < KS) {
            asm volatile("cp.async.wait_group 1;" ::: "memory");
        } else {
            asm volatile("cp.async.wait_group 0;" ::: "memory");
        }
        __syncthreads();
        if (i + 2 < KS) LOAD_SLAB(i + 2);

        const __half* As = smh + (i % 3) * STAGE_H;
        const __half* Bs = As + STG_H;

#pragma unroll
        for (int kk = 0; kk < 4; kk++) {
            int kb = kk * 16;
            uint32_t a[4][4], b[4][2];
#pragma unroll
            for (int mi = 0; mi < 4; mi++) {
                int r0 = wm + mi * 16 + gid;
                a[mi][0] = *(const uint32_t*)&As[(r0    ) * KPAD_H + kb + 2 * tig    ];
                a[mi][1] = *(const uint32_t*)&As[(r0 + 8) * KPAD_H + kb + 2 * tig    ];
                a[mi][2] = *(const uint32_t*)&As[(r0    ) * KPAD_H + kb + 2 * tig + 8];
                a[mi][3] = *(const uint32_t*)&As[(r0 + 8) * KPAD_H + kb + 2 * tig + 8];
            }
#pragma unroll
            for (int ni = 0; ni < 4; ni++) {
                int c0 = wn + ni * 8 + gid;
                b[ni][0] = *(const uint32_t*)&Bs[c0 * KPAD_H + kb + 2 * tig    ];
                b[ni][1] = *(const uint32_t*)&Bs[c0 * KPAD_H + kb + 2 * tig + 8];
            }
#pragma unroll
            for (int mi = 0; mi < 4; mi++)
#pragma unroll
                for (int ni = 0; ni < 4; ni++)
                    mma_f16(acc[mi][ni], a[mi], b[ni]);
        }
    }

    // ---- epilogue ----
    if (EPI == 4 && n0 >= 2 * CEMB) {
        __syncthreads();
#pragma unroll
        for (int mi = 0; mi < 4; mi++) {
#pragma unroll
            for (int half_ = 0; half_ < 2; half_++) {
                int lrow = wm + mi * 16 + gid + half_ * 8;
#pragma unroll
                for (int ni = 0; ni < 4; ni++) {
                    int lcol = wn + ni * 8 + tig * 2;
                    float vx = acc[mi][ni][half_ * 2 + 0];
                    float vy = acc[mi][ni][half_ * 2 + 1];
                    smh[(lcol    ) * VSTG_PAD + lrow] = __float2half_rn(vx);
                    smh[(lcol + 1) * VSTG_PAD + lrow] = __float2half_rn(vy);
                }
            }
        }
        __syncthreads();

        int b_ = m0 / TT;
        int t_base = m0 % TT;
        int cc0 = n0 - 2 * CEMB;
#pragma unroll
        for (int it = 0; it < 8; it++) {
            int idx = it * 256 + tid;
            int l  = idx >> 4;
            int ch = idx & 15;
            int gcol = cc0 + l;
            __half* dst = vTp +
                ((size_t)(b_ * NH + (gcol >> 6)) * HD + (gcol & 63)) * TT
                + t_base + ch * 8;
            *(float4*)dst = *(const float4*)&smh[l * VSTG_PAD + ch * 8];
        }
        return;
    }

#pragma unroll
    for (int mi = 0; mi < 4; mi++) {
        int row0 = m0 + wm + mi * 16 + gid;
#pragma unroll
        for (int half_ = 0; half_ < 2; half_++) {
            int row = row0 + half_ * 8;
#pragma unroll
            for (int ni = 0; ni < 4; ni++) {
                int col = n0 + wn + ni * 8 + tig * 2;
                float vx = acc[mi][ni][half_ * 2 + 0];
                float vy = acc[mi][ni][half_ * 2 + 1];
                if (EPI == 1) {
                    float* C = (float*)Cv;
                    float2 rr = *(const float2*)&R[(size_t)row * N + col];
                    float2 v; v.x = vx + rr.x; v.y = vy + rr.y;
                    *(float2*)&C[(size_t)row * N + col] = v;
                } else {
                    if (EPI == 2) {
                        vx = 0.5f * vx * (1.0f + erff(vx * 0.70710678118654752f));
                        vy = 0.5f * vy * (1.0f + erff(vy * 0.70710678118654752f));
                    }
                    __half* C = (__half*)Cv;
                    *(uint32_t*)&C[(size_t)row * N + col] = packh2(vx, vy);
                }
            }
        }
    }
#undef LOAD_SLAB
}

// ---------------- n64 v1: 128x64 CTA tile, 4 warps, 64x32 warp tile ------
__global__ __launch_bounds__(128) void mma_gemm_n64(
    const __half* __restrict__ A, const __half* __restrict__ Bt,
    const float* __restrict__ R, float* __restrict__ C,
    int M, int N, int K)
{
    extern __shared__ __half smh[];

    int tid  = threadIdx.x;
    int wid  = tid >> 5;
    int lane = tid & 31;
    int gid  = lane >> 2;
    int tig  = lane & 3;

    int m0 = blockIdx.y * 128, n0 = blockIdx.x * 64;
    int wm = (wid >> 1) * 64;
    int wn = (wid & 1) * 32;

    uint32_t su = smem_u32(smh);

    float acc[4][4][4];
#pragma unroll
    for (int mi = 0; mi < 4; mi++)
#pragma unroll
        for (int ni = 0; ni < 4; ni++)
#pragma unroll
            for (int r = 0; r < 4; r++) acc[mi][ni][r] = 0.f;

    const int KS = K / BK;

#define LOAD_SLAB64(i) do {                                                 \
    int _k0 = (i) * BK;                                                     \
    uint32_t base = su + (uint32_t)((i) & 1) * (STAGE64_H * 2);             \
    _Pragma("unroll")                                                       \
    for (int it = 0; it < 8; it++) {                                        \
        int idx = it * 128 + tid;                                           \
        int r = idx >> 3, c = idx & 7;                                      \
        cp16(base + (uint32_t)r * (KPAD_H * 2) + (uint32_t)c * 16,          \
             A + (size_t)(m0 + r) * K + _k0 + c * 8);                       \
    }                                                                       \
    _Pragma("unroll")                                                       \
    for (int it = 0; it < 4; it++) {                                        \
        int idx = it * 128 + tid;                                           \
        int r = idx >> 3, c = idx & 7;                                      \
        cp16(base + (STGA64_H * 2) + (uint32_t)r * (KPAD_H * 2)             \
             + (uint32_t)c * 16,                                            \
             Bt + (size_t)(n0 + r) * K + _k0 + c * 8);                      \
    }                                                                       \
    asm volatile("cp.async.commit_group;" ::: "memory");                    \
} while (0)

    LOAD_SLAB64(0);

    for (int i = 0; i < KS; i++) {
        if (i + 1 < KS) {
            LOAD_SLAB64(i + 1);
            asm volatile("cp.async.wait_group 1;" ::: "memory");
        } else {
            asm volatile("cp.async.wait_group 0;" ::: "memory");
        }
        __syncthreads();

        const __half* As = smh + (i & 1) * STAGE64_H;
        const __half* Bs = As + STGA64_H;

#pragma unroll
        for (int kk = 0; kk < 4; kk++) {
            int kb = kk * 16;
            uint32_t a[4][4], b[4][2];
#pragma unroll
            for (int mi = 0; mi < 4; mi++) {
                int r0 = wm + mi * 16 + gid;
                a[mi][0] = *(const uint32_t*)&As[(r0    ) * KPAD_H + kb + 2 * tig    ];
                a[mi][1] = *(const uint32_t*)&As[(r0 + 8) * KPAD_H + kb + 2 * tig    ];
                a[mi][2] = *(const uint32_t*)&As[(r0    ) * KPAD_H + kb + 2 * tig + 8];
                a[mi][3] = *(const uint32_t*)&As[(r0 + 8) * KPAD_H + kb + 2 * tig + 8];
            }
#pragma unroll
            for (int ni = 0; ni < 4; ni++) {
                int c0 = wn + ni * 8 + gid;
                b[ni][0] = *(const uint32_t*)&Bs[c0 * KPAD_H + kb + 2 * tig    ];
                b[ni][1] = *(const uint32_t*)&Bs[c0 * KPAD_H + kb + 2 * tig + 8];
            }
#pragma unroll
            for (int mi = 0; mi < 4; mi++)
#pragma unroll
                for (int ni = 0; ni < 4; ni++)
                    mma_f16(acc[mi][ni], a[mi], b[ni]);
        }
        __syncthreads();
    }

#pragma unroll
    for (int mi = 0; mi < 4; mi++) {
        int row0 = m0 + wm + mi * 16 + gid;
#pragma unroll
        for (int half_ = 0; half_ < 2; half_++) {
            int row = row0 + half_ * 8;
#pragma unroll
            for (int ni = 0; ni < 4; ni++) {
                int col = n0 + wn + ni * 8 + tig * 2;
                float vx = acc[mi][ni][half_ * 2 + 0];
                float vy = acc[mi][ni][half_ * 2 + 1];
                float2 rr = *(const float2*)&R[(size_t)row * N + col];
                float2 v; v.x = vx + rr.x; v.y = vy + rr.y;
                *(float2*)&C[(size_t)row * N + col] = v;
            }
        }
    }
#undef LOAD_SLAB64
}

// ---------------- MMA flash attention (causal, fp16) ---------------------
// R11 config; trailing __syncthreads removed (3-buffer ring makes it
// redundant: top sync of iter i already orders iter i-1's reads before
// the prefetch of buffer (i+2)%3).
__global__ __launch_bounds__(256) void attn_mma(
    const __half* __restrict__ qkv, const __half* __restrict__ vT,
    __half* __restrict__ y)
{
    extern __shared__ __half smh[];
    int tid  = threadIdx.x;
    int wid  = tid >> 5;
    int lane = tid & 31;
    int gid  = lane >> 2;
    int tig  = lane & 3;

    int qt = blockIdx.x;
    int h = blockIdx.y, b = blockIdx.z;
    int q0 = qt * QT;
    int ntiles = 2 * qt + 2;

    const __half* qbase = qkv + (size_t)b * TT * C3 + h * HD;
    const __half* kbase = qkv + (size_t)b * TT * C3 + CEMB + h * HD;
    const __half* vbase = vT + (size_t)(b * NH + h) * HD * TT;

    uint32_t su = smem_u32(smh);

#pragma unroll
    for (int it = 0; it < 4; it++) {
        int idx = it * 256 + tid;
        int r = idx >> 3, c = idx & 7;
        cp16(su + (uint32_t)(r * APAD_H + c * 8) * 2,
             qbase + (size_t)(q0 + r) * C3 + c * 8);
    }

#define LOAD_KV(k0, s) do {                                                  \
    uint32_t kdst = su + (uint32_t)(QS_H + (s) * ASTG_H) * 2;                \
    uint32_t vdst = kdst + KV_H * 2;                                         \
    _Pragma("unroll")                                                        \
    for (int it = 0; it < 2; it++) {                                         \
        int idx = it * 256 + tid;                                            \
        int r = idx >> 3, c = idx & 7;                                       \
        uint32_t off = (uint32_t)(r * APAD_H + c * 8) * 2;                   \
        cp16(kdst + off, kbase + (size_t)((k0) + r) * C3 + c * 8);           \
        cp16(vdst + off, vbase + (size_t)r * TT + (k0) + c * 8);             \
    }                                                                        \
    asm volatile("cp.async.commit_group;" ::: "memory");                     \
} while (0)

    LOAD_KV(0, 0);
    LOAD_KV(KT, 1);

    uint32_t qf[4][4];
    float o[8][4];
#pragma unroll
    for (int ni = 0; ni < 8; ni++)
#pragma unroll
        for (int r = 0; r < 4; r++) o[ni][r] = 0.f;
    float m0v = -INFINITY, m1v = -INFINITY, l0 = 0.f, l1 = 0.f;

    int rw = wid * 16 + gid;
    const __half2 hscale = __float2half2_rn(0.125f);

    for (int i = 0; i < ntiles; i++) {
        if (i < ntiles - 1) {
            asm volatile("cp.async.wait_group 1;" ::: "memory");
        } else {
            asm volatile("cp.async.wait_group 0;" ::: "memory");
        }
        __syncthreads();

        if (i + 2 < ntiles) LOAD_KV((i + 2) * KT, (i + 2) % 3);

        if (i == 0) {
#pragma unroll
            for (int kk = 0; kk < 4; kk++) {
                int kb = kk * 16;
                __half2 h0 = __hmul2(*(const __half2*)&smh[(rw    ) * APAD_H + kb + 2 * tig    ], hscale);
                __half2 h1 = __hmul2(*(const __half2*)&smh[(rw + 8) * APAD_H + kb + 2 * tig    ], hscale);
                __half2 h2 = __hmul2(*(const __half2*)&smh[(rw    ) * APAD_H + kb + 2 * tig + 8], hscale);
                __half2 h3 = __hmul2(*(const __half2*)&smh[(rw + 8) * APAD_H + kb + 2 * tig + 8], hscale);
                qf[kk][0] = *(uint32_t*)&h0; qf[kk][1] = *(uint32_t*)&h1;
                qf[kk][2] = *(uint32_t*)&h2; qf[kk][3] = *(uint32_t*)&h3;
            }
        }

        int k0 = i * KT;
        bool active = (q0 + wid * 16 + 15) >= k0;
        if (active) {
            const __half* Ks = smh + QS_H + (i % 3) * ASTG_H;
            const __half* Vs = Ks + KV_H;

            float sacc[8][4];
#pragma unroll
            for (int ni = 0; ni < 8; ni++)
#pragma unroll
                for (int r = 0; r < 4; r++) sacc[ni][r] = 0.f;

#pragma unroll
            for (int kk = 0; kk < 4; kk++) {
                int kb = kk * 16;
#pragma unroll
                for (int ni = 0; ni < 8; ni++) {
                    uint32_t bb[2];
                    bb[0] = *(const uint32_t*)&Ks[(ni * 8 + gid) * APAD_H + kb + 2 * tig    ];
                    bb[1] = *(const uint32_t*)&Ks[(ni * 8 + gid) * APAD_H + kb + 2 * tig + 8];
                    mma_f16(sacc[ni], qf[kk], bb);
                }
            }

            if (i >= ntiles - 2) {
                int row0 = q0 + rw;
#pragma unroll
                for (int ni = 0; ni < 8; ni++) {
#pragma unroll
                    for (int r = 0; r < 4; r++) {
                        int col = k0 + ni * 8 + 2 * tig + (r & 1);
                        int row = row0 + ((r >= 2) ? 8 : 0);
                        if (col > row) sacc[ni][r] = -INFINITY;
                    }
                }
            }

            float t0 = -INFINITY, t1 = -INFINITY;
#pragma unroll
            for (int ni = 0; ni < 8; ni++) {
                t0 = fmaxf(t0, fmaxf(sacc[ni][0], sacc[ni][1]));
                t1 = fmaxf(t1, fmaxf(sacc[ni][2], sacc[ni][3]));
            }
            t0 = fmaxf(t0, __shfl_xor_sync(0xffffffffu, t0, 1));
            t0 = fmaxf(t0, __shfl_xor_sync(0xffffffffu, t0, 2));
            t1 = fmaxf(t1, __shfl_xor_sync(0xffffffffu, t1, 1));
            t1 = fmaxf(t1, __shfl_xor_sync(0xffffffffu, t1, 2));

            float mn0 = fmaxf(m0v, t0), mn1 = fmaxf(m1v, t1);
            float al0 = exp2f((m0v - mn0) * LOG2E);
            float al1 = exp2f((m1v - mn1) * LOG2E);
            m0v = mn0; m1v = mn1;
            l0 *= al0;  l1 *= al1;
#pragma unroll
            for (int ni = 0; ni < 8; ni++) {
                o[ni][0] *= al0; o[ni][1] *= al0;
                o[ni][2] *= al1; o[ni][3] *= al1;
            }

            uint32_t pf[4][4];
#pragma unroll
            for (int kk = 0; kk < 4; kk++) {
                float p00 = exp2f((sacc[2 * kk    ][0] - mn0) * LOG2E);
                float p01 = exp2f((sacc[2 * kk    ][1] - mn0) * LOG2E);
                float p02 = exp2f((sacc[2 * kk    ][2] - mn1) * LOG2E);
                float p03 = exp2f((sacc[2 * kk    ][3] - mn1) * LOG2E);
                float p10 = exp2f((sacc[2 * kk + 1][0] - mn0) * LOG2E);
                float p11 = exp2f((sacc[2 * kk + 1][1] - mn0) * LOG2E);
                float p12 = exp2f((sacc[2 * kk + 1][2] - mn1) * LOG2E);
                float p13 = exp2f((sacc[2 * kk + 1][3] - mn1) * LOG2E);
                l0 += p00 + p01 + p10 + p11;
                l1 += p02 + p03 + p12 + p13;
                pf[kk][0] = packh2(p00, p01);
                pf[kk][1] = packh2(p02, p03);
                pf[kk][2] = packh2(p10, p11);
                pf[kk][3] = packh2(p12, p13);
            }

#pragma unroll
            for (int kk = 0; kk < 4; kk++) {
                int kb = kk * 16;
#pragma unroll
                for (int ni = 0; ni < 8; ni++) {
                    uint32_t bb[2];
                    bb[0] = *(const uint32_t*)&Vs[(ni * 8 + gid) * APAD_H + kb + 2 * tig    ];
                    bb[1] = *(const uint32_t*)&Vs[(ni * 8 + gid) * APAD_H + kb + 2 * tig + 8];
                    mma_f16(o[ni], pf[kk], bb);
                }
            }
        }
        // no trailing __syncthreads: 3-buffer ring + top sync make it redundant
    }

    l0 += __shfl_xor_sync(0xffffffffu, l0, 1);
    l0 += __shfl_xor_sync(0xffffffffu, l0, 2);
    l1 += __shfl_xor_sync(0xffffffffu, l1, 1);
    l1 += __shfl_xor_sync(0xffffffffu, l1, 2);
    float r0 = 1.0f / l0, r1 = 1.0f / l1;

    int grow0 = (b * TT + q0 + rw);
#pragma unroll
    for (int ni = 0; ni < 8; ni++) {
        int col = h * HD + ni * 8 + 2 * tig;
        *(uint32_t*)&y[(size_t)grow0 * CEMB + col]       = packh2(o[ni][0] * r0, o[ni][1] * r0);
        *(uint32_t*)&y[(size_t)(grow0 + 8) * CEMB + col] = packh2(o[ni][2] * r1, o[ni][3] * r1);
    }
#undef LOAD_KV
}

// ---------------- launch ----------------
extern "C" void kernel_launch(void* const* d_in, const int* in_sizes, int n_in,
                              void* d_out, int out_size)
{
    (void)in_sizes; (void)n_in; (void)out_size;
    const float* x      = (const float*)d_in[0];
    const float* ln1_g  = (const float*)d_in[1];
    const float* ln1_b  = (const float*)d_in[2];
    const float* W_attn = (const float*)d_in[3];
    const float* W_o    = (const float*)d_in[4];
    const float* ln2_g  = (const float*)d_in[5];
    const float* ln2_b  = (const float*)d_in[6];
    const float* W_fc   = (const float*)d_in[7];
    const float* W_proj = (const float*)d_in[8];
    float* out = (float*)d_out;

    __half *p_ln, *p_qkv, *p_vT, *p_att, *p_h;
    __half *p_wattT, *p_woT, *p_wfcT, *p_wprojT;
    float *p_x1;
    cudaGetSymbolAddress((void**)&p_ln,     g_ln);
    cudaGetSymbolAddress((void**)&p_qkv,    g_qkv);
    cudaGetSymbolAddress((void**)&p_vT,     g_vT);
    cudaGetSymbolAddress((void**)&p_att,    g_att);
    cudaGetSymbolAddress((void**)&p_x1,     g_x1);
    cudaGetSymbolAddress((void**)&p_h,      g_h);
    cudaGetSymbolAddress((void**)&p_wattT,  g_wattT);
    cudaGetSymbolAddress((void**)&p_woT,    g_woT);
    cudaGetSymbolAddress((void**)&p_wfcT,   g_wfcT);
    cudaGetSymbolAddress((void**)&p_wprojT, g_wprojT);

    cudaFuncSetAttribute(mma_gemm<2>, cudaFuncAttributeMaxDynamicSharedMemorySize, GEMM_SMEM);
    cudaFuncSetAttribute(mma_gemm<4>, cudaFuncAttributeMaxDynamicSharedMemorySize, GEMM_SMEM);
    cudaFuncSetAttribute(mma_gemm_n64, cudaFuncAttributeMaxDynamicSharedMemorySize, GEMM64_SMEM);
    cudaFuncSetAttribute(attn_mma, cudaFuncAttributeMaxDynamicSharedMemorySize, ATT_SMEM);

    // 0. fused prep: all weight transposes + ln1 in one launch
    prep_kernel<<<PREP_TOTAL, 256>>>(W_attn, W_o, W_fc, W_proj,
                                     p_wattT, p_woT, p_wfcT, p_wprojT,
                                     x, ln1_g, ln1_b, p_ln);

    // 2. qkv = ln1 @ W_attn; Q,K to g_qkv, V staged+transposed to g_vT
    mma_gemm<4><<<dim3(C3 / 128, BT / 128), 256, GEMM_SMEM>>>(
        p_ln, p_wattT, nullptr, p_qkv, p_vT, BT, C3, CEMB);

    // 3. MMA flash attention (half out)
    attn_mma<<<dim3(TT / QT, NH, NB), 256, ATT_SMEM>>>(p_qkv, p_vT, p_att);

    // 4. x1 = att @ W_o + x (float out, n64 v1)
    mma_gemm_n64<<<dim3(CEMB / 64, BT / 128), 128, GEMM64_SMEM>>>(
        p_att, p_woT, x, p_x1, BT, CEMB, CEMB);

    // 5. ln2
    ln_kernel<<<BT, 256>>>(p_x1, ln2_g, ln2_b, p_ln);

    // 6. h = gelu(ln2 @ W_fc) (half out)
    mma_gemm<2><<<dim3(HID / 128, BT / 128), 256, GEMM_SMEM>>>(
        p_ln, p_wfcT, nullptr, p_h, nullptr, BT, HID, CEMB);

    // 7. out = h @ W_proj + x1 (float out, n64 v1)
    mma_gemm_n64<<<dim3(CEMB / 64, BT / 128), 128, GEMM64_SMEM>>>(
        p_h, p_wprojT, p_x1, out, BT, CEMB, HID);
}

// round 16
// speedup vs baseline: 1.0397x; 1.0025x over previous
#include <cuda_runtime.h>
#include <cuda_fp16.h>
#include <math.h>
#include <stdint.h>

// ---------------- problem constants ----------------
#define NB   4
#define TT   2048
#define CEMB 768
#define C3   (3 * CEMB)       // 2304
#define HID  (4 * CEMB)       // 3072
#define NH   12
#define HD   64
#define BT   (NB * TT)        // 8192
#define LNEPS 1e-5f
#define LOG2E 1.4426950408889634f

// GEMM tiling (halves): BK=64, 3 stages, single barrier per slab
#define BK      64
#define KPAD_H  72
#define STG_H   (128 * KPAD_H)         // 9216 halves per operand per stage
#define STAGE_H (2 * STG_H)            // 18432 halves (A+B)
#define GEMM_SMEM (3 * STAGE_H * 2)    // 110592 bytes

// n64 GEMM variant v1 (128x64 CTA tile, 4 warps, 64x32 warp tile, 2 stages)
#define STGA64_H (128 * KPAD_H)        // 9216
#define STGB64_H (64 * KPAD_H)         // 4608
#define STAGE64_H (STGA64_H + STGB64_H)  // 13824
#define GEMM64_SMEM (2 * STAGE64_H * 2)  // 55296 bytes

// V-stage transpose pad (halves)
#define VSTG_PAD 136

// attention tiling (halves)
#define QT     128
#define KT     64
#define APAD_H 72
#define QS_H   (QT * APAD_H)           // 9216
#define KV_H   (KT * APAD_H)           // 4608
#define ASTG_H (2 * KV_H)              // 9216
#define ATT_SMEM ((QS_H + 3 * ASTG_H) * 2)   // 73728 bytes

// ---------------- scratch ----------------
__device__ __half g_ln [BT * CEMB];
__device__ __half g_qkv[BT * C3];
__device__ __half g_vT [NB * NH * HD * TT];
__device__ __half g_att[BT * CEMB];
__device__ float  g_x1 [BT * CEMB];
__device__ __half g_h  [BT * HID];
__device__ __half g_wattT [C3 * CEMB];
__device__ __half g_woT   [CEMB * CEMB];
__device__ __half g_wfcT  [HID * CEMB];
__device__ __half g_wprojT[CEMB * HID];

// ---------------- helpers ----------------
__device__ __forceinline__ uint32_t smem_u32(const void* p) {
    uint32_t a;
    asm("{ .reg .u64 t; cvta.to.shared.u64 t, %1; cvt.u32.u64 %0, t; }"
        : "=r"(a) : "l"(p));
    return a;
}

__device__ __forceinline__ void cp16(uint32_t sa, const void* ga) {
    asm volatile("cp.async.cg.shared.global [%0], [%1], 16;"
                 :: "r"(sa), "l"(ga));
}

__device__ __forceinline__ void mma_f16(float* d, const uint32_t* a,
                                        const uint32_t* b) {
    asm volatile(
        "mma.sync.aligned.m16n8k16.row.col.f32.f16.f16.f32 "
        "{%0,%1,%2,%3}, {%4,%5,%6,%7}, {%8,%9}, {%0,%1,%2,%3};"
        : "+f"(d[0]), "+f"(d[1]), "+f"(d[2]), "+f"(d[3])
        : "r"(a[0]), "r"(a[1]), "r"(a[2]), "r"(a[3]),
          "r"(b[0]), "r"(b[1]));
}

__device__ __forceinline__ uint32_t packh2(float x, float y) {
    __half2 h = __float22half2_rn(make_float2(x, y));
    return *(uint32_t*)&h;
}

// ---------------- fused prep: 4 weight transposes + ln1 (one launch) -----
#define TR_T0 1728
#define TR_T1 (TR_T0 + 576)    // 2304
#define TR_T2 (TR_T1 + 2304)   // 4608
#define TR_TOTAL (TR_T2 + 2304) // 6912
#define PREP_TOTAL (TR_TOTAL + BT)  // 15104
__global__ __launch_bounds__(256) void prep_kernel(
    const float* __restrict__ W0, const float* __restrict__ W1,
    const float* __restrict__ W2, const float* __restrict__ W3,
    __half* __restrict__ T0, __half* __restrict__ T1,
    __half* __restrict__ T2, __half* __restrict__ T3,
    const float* __restrict__ x, const float* __restrict__ lng,
    const float* __restrict__ lnb, __half* __restrict__ lnout)
{
    int id = blockIdx.x;
    int tid = threadIdx.x;

    if (id >= TR_TOTAL) {
        int row = id - TR_TOTAL;
        const float* xr = x + (size_t)row * CEMB;

        float v[3];
#pragma unroll
        for (int i = 0; i < 3; i++) v[i] = xr[tid + i * 256];

        float s = v[0] + v[1] + v[2];
        float q = v[0] * v[0] + v[1] * v[1] + v[2] * v[2];

        __shared__ float ssum[8], ssq[8];
#pragma unroll
        for (int o = 16; o > 0; o >>= 1) {
            s += __shfl_xor_sync(0xffffffffu, s, o);
            q += __shfl_xor_sync(0xffffffffu, q, o);
        }
        if ((tid & 31) == 0) { ssum[tid >> 5] = s; ssq[tid >> 5] = q; }
        __syncthreads();
        if (tid < 32) {
            s = (tid < 8) ? ssum[tid] : 0.f;
            q = (tid < 8) ? ssq [tid] : 0.f;
#pragma unroll
            for (int o = 4; o > 0; o >>= 1) {
                s += __shfl_xor_sync(0xffffffffu, s, o);
                q += __shfl_xor_sync(0xffffffffu, q, o);
            }
            if (tid == 0) { ssum[0] = s; ssq[0] = q; }
        }
        __syncthreads();

        float mean = ssum[0] * (1.0f / CEMB);
        float var  = ssq[0]  * (1.0f / CEMB) - mean * mean;
        float rstd = rsqrtf(var + LNEPS);

        __half* orow = lnout + (size_t)row * CEMB;
#pragma unroll
        for (int i = 0; i < 3; i++) {
            int c = tid + i * 256;
            orow[c] = __float2half_rn((v[i] - mean) * rstd * lng[c] + lnb[c]);
        }
        return;
    }

    const float* W; __half* WT; int K, N, bx, by, t;
    if (id < TR_T0)       { W = W0; WT = T0; K = CEMB; N = C3;
                            t = id;          bx = t % 72; by = t / 72; }
    else if (id < TR_T1)  { W = W1; WT = T1; K = CEMB; N = CEMB;
                            t = id - TR_T0;  bx = t % 24; by = t / 24; }
    else if (id < TR_T2)  { W = W2; WT = T2; K = CEMB; N = HID;
                            t = id - TR_T1;  bx = t % 96; by = t / 96; }
    else                  { W = W3; WT = T3; K = HID;  N = CEMB;
                            t = id - TR_T2;  bx = t % 24; by = t / 24; }
    bx *= 32; by *= 32;

    __shared__ float tb[32][33];
    int tx = tid & 31, ty = tid >> 5;
#pragma unroll
    for (int i = 0; i < 32; i += 8)
        tb[ty + i][tx] = W[(size_t)(by + ty + i) * N + bx + tx];
    __syncthreads();
#pragma unroll
    for (int i = 0; i < 32; i += 8)
        WT[(size_t)(bx + ty + i) * K + by + tx] = __float2half_rn(tb[tx][ty + i]);
}

// ---------------- layernorm (fp32 in, fp16 out) ----------------
__global__ __launch_bounds__(256) void ln_kernel(
    const float* __restrict__ x, const float* __restrict__ g,
    const float* __restrict__ b, __half* __restrict__ out)
{
    int row = blockIdx.x;
    int tid = threadIdx.x;
    const float* xr = x + (size_t)row * CEMB;

    float v[3];
#pragma unroll
    for (int i = 0; i < 3; i++) v[i] = xr[tid + i * 256];

    float s = v[0] + v[1] + v[2];
    float q = v[0] * v[0] + v[1] * v[1] + v[2] * v[2];

    __shared__ float ssum[8], ssq[8];
#pragma unroll
    for (int o = 16; o > 0; o >>= 1) {
        s += __shfl_xor_sync(0xffffffffu, s, o);
        q += __shfl_xor_sync(0xffffffffu, q, o);
    }
    if ((tid & 31) == 0) { ssum[tid >> 5] = s; ssq[tid >> 5] = q; }
    __syncthreads();
    if (tid < 32) {
        s = (tid < 8) ? ssum[tid] : 0.f;
        q = (tid < 8) ? ssq [tid] : 0.f;
#pragma unroll
        for (int o = 4; o > 0; o >>= 1) {
            s += __shfl_xor_sync(0xffffffffu, s, o);
            q += __shfl_xor_sync(0xffffffffu, q, o);
        }
        if (tid == 0) { ssum[0] = s; ssq[0] = q; }
    }
    __syncthreads();

    float mean = ssum[0] * (1.0f / CEMB);
    float var  = ssq[0]  * (1.0f / CEMB) - mean * mean;
    float rstd = rsqrtf(var + LNEPS);

    __half* orow = out + (size_t)row * CEMB;
#pragma unroll
    for (int i = 0; i < 3; i++) {
        int c = tid + i * 256;
        orow[c] = __float2half_rn((v[i] - mean) * rstd * g[c] + b[c]);
    }
}

// ---------------- mma.sync fp16 GEMM: C = A[M,K] @ Bt[N,K]^T (+epi) ------
// EPI: 1 -> float out + residual R, 2 -> gelu + half out,
//      4 -> qkv mode: QK cols to C; V tiles staged in smem, coalesced to vTp
template <int EPI>
__global__ __launch_bounds__(256) void mma_gemm(
    const __half* __restrict__ A, const __half* __restrict__ Bt,
    const float* __restrict__ R, void* __restrict__ Cv,
    __half* __restrict__ vTp,
    int M, int N, int K)
{
    extern __shared__ __half smh[];

    int tid  = threadIdx.x;
    int wid  = tid >> 5;
    int lane = tid & 31;
    int gid  = lane >> 2;
    int tig  = lane & 3;

    int m0 = blockIdx.y * 128, n0 = blockIdx.x * 128;
    int wm = (wid >> 2) * 64;
    int wn = (wid & 3) * 32;

    uint32_t su = smem_u32(smh);

    float acc[4][4][4];
#pragma unroll
    for (int mi = 0; mi < 4; mi++)
#pragma unroll
        for (int ni = 0; ni < 4; ni++)
#pragma unroll
            for (int r = 0; r < 4; r++) acc[mi][ni][r] = 0.f;

    const int KS = K / BK;

#define LOAD_SLAB(i) do {                                                   \
    int _k0 = (i) * BK;                                                     \
    uint32_t base = su + (uint32_t)((i) % 3) * (STAGE_H * 2);               \
    _Pragma("unroll")                                                       \
    for (int it = 0; it < 4; it++) {                                        \
        int idx = it * 256 + tid;                                           \
        int r = idx >> 3, c = idx & 7;                                      \
        uint32_t off = (uint32_t)r * (KPAD_H * 2) + (uint32_t)c * 16;       \
        cp16(base + off,                                                    \
             A  + (size_t)(m0 + r) * K + _k0 + c * 8);                      \
        cp16(base + (STG_H * 2) + off,                                      \
             Bt + (size_t)(n0 + r) * K + _k0 + c * 8);                      \
    }                                                                       \
    asm volatile("cp.async.commit_group;" ::: "memory");                    \
} while (0)

    LOAD_SLAB(0);
    LOAD_SLAB(1);

    for (int i = 0; i < KS; i++) {
        if (i + 1 < KS) {
            asm volatile("cp.async.wait_group 1;" ::: "memory");
        } else {
            asm volatile("cp.async.wait_group 0;" ::: "memory");
        }
        __syncthreads();
        if (i + 2 < KS) LOAD_SLAB(i + 2);

        const __half* As = smh + (i % 3) * STAGE_H;
        const __half* Bs = As + STG_H;

#pragma unroll
        for (int kk = 0; kk < 4; kk++) {
            int kb = kk * 16;
            uint32_t a[4][4], b[4][2];
#pragma unroll
            for (int mi = 0; mi < 4; mi++) {
                int r0 = wm + mi * 16 + gid;
                a[mi][0] = *(const uint32_t*)&As[(r0    ) * KPAD_H + kb + 2 * tig    ];
                a[mi][1] = *(const uint32_t*)&As[(r0 + 8) * KPAD_H + kb + 2 * tig    ];
                a[mi][2] = *(const uint32_t*)&As[(r0    ) * KPAD_H + kb + 2 * tig + 8];
                a[mi][3] = *(const uint32_t*)&As[(r0 + 8) * KPAD_H + kb + 2 * tig + 8];
            }
#pragma unroll
            for (int ni = 0; ni < 4; ni++) {
                int c0 = wn + ni * 8 + gid;
                b[ni][0] = *(const uint32_t*)&Bs[c0 * KPAD_H + kb + 2 * tig    ];
                b[ni][1] = *(const uint32_t*)&Bs[c0 * KPAD_H + kb + 2 * tig + 8];
            }
#pragma unroll
            for (int mi = 0; mi < 4; mi++)
#pragma unroll
                for (int ni = 0; ni < 4; ni++)
                    mma_f16(acc[mi][ni], a[mi], b[ni]);
        }
    }

    // ---- epilogue ----
    if (EPI == 4 && n0 >= 2 * CEMB) {
        __syncthreads();
#pragma unroll
        for (int mi = 0; mi < 4; mi++) {
#pragma unroll
            for (int half_ = 0; half_ < 2; half_++) {
                int lrow = wm + mi * 16 + gid + half_ * 8;
#pragma unroll
                for (int ni = 0; ni < 4; ni++) {
                    int lcol = wn + ni * 8 + tig * 2;
                    float vx = acc[mi][ni][half_ * 2 + 0];
                    float vy = acc[mi][ni][half_ * 2 + 1];
                    smh[(lcol    ) * VSTG_PAD + lrow] = __float2half_rn(vx);
                    smh[(lcol + 1) * VSTG_PAD + lrow] = __float2half_rn(vy);
                }
            }
        }
        __syncthreads();

        int b_ = m0 / TT;
        int t_base = m0 % TT;
        int cc0 = n0 - 2 * CEMB;
#pragma unroll
        for (int it = 0; it < 8; it++) {
            int idx = it * 256 + tid;
            int l  = idx >> 4;
            int ch = idx & 15;
            int gcol = cc0 + l;
            __half* dst = vTp +
                ((size_t)(b_ * NH + (gcol >> 6)) * HD + (gcol & 63)) * TT
                + t_base + ch * 8;
            *(float4*)dst = *(const float4*)&smh[l * VSTG_PAD + ch * 8];
        }
        return;
    }

#pragma unroll
    for (int mi = 0; mi < 4; mi++) {
        int row0 = m0 + wm + mi * 16 + gid;
#pragma unroll
        for (int half_ = 0; half_ < 2; half_++) {
            int row = row0 + half_ * 8;
#pragma unroll
            for (int ni = 0; ni < 4; ni++) {
                int col = n0 + wn + ni * 8 + tig * 2;
                float vx = acc[mi][ni][half_ * 2 + 0];
                float vy = acc[mi][ni][half_ * 2 + 1];
                if (EPI == 1) {
                    float* C = (float*)Cv;
                    float2 rr = *(const float2*)&R[(size_t)row * N + col];
                    float2 v; v.x = vx + rr.x; v.y = vy + rr.y;
                    *(float2*)&C[(size_t)row * N + col] = v;
                } else {
                    if (EPI == 2) {
                        vx = 0.5f * vx * (1.0f + erff(vx * 0.70710678118654752f));
                        vy = 0.5f * vy * (1.0f + erff(vy * 0.70710678118654752f));
                    }
                    __half* C = (__half*)Cv;
                    *(uint32_t*)&C[(size_t)row * N + col] = packh2(vx, vy);
                }
            }
        }
    }
#undef LOAD_SLAB
}

// ---------------- n64 v1b: 128x64 CTA tile, 4 warps, 64x32 warp tile -----
// 2 stages, SINGLE barrier per slab: wait -> sync -> prefetch(i+1) -> compute.
// Safe with 2 buffers: top sync of iter i orders compute(i-1), the last
// reader of buffer (i+1)&1, before the prefetch into it.
__global__ __launch_bounds__(128) void mma_gemm_n64(
    const __half* __restrict__ A, const __half* __restrict__ Bt,
    const float* __restrict__ R, float* __restrict__ C,
    int M, int N, int K)
{
    extern __shared__ __half smh[];

    int tid  = threadIdx.x;
    int wid  = tid >> 5;
    int lane = tid & 31;
    int gid  = lane >> 2;
    int tig  = lane & 3;

    int m0 = blockIdx.y * 128, n0 = blockIdx.x * 64;
    int wm = (wid >> 1) * 64;
    int wn = (wid & 1) * 32;

    uint32_t su = smem_u32(smh);

    float acc[4][4][4];
#pragma unroll
    for (int mi = 0; mi < 4; mi++)
#pragma unroll
        for (int ni = 0; ni < 4; ni++)
#pragma unroll
            for (int r = 0; r < 4; r++) acc[mi][ni][r] = 0.f;

    const int KS = K / BK;

#define LOAD_SLAB64(i) do {                                                 \
    int _k0 = (i) * BK;                                                     \
    uint32_t base = su + (uint32_t)((i) & 1) * (STAGE64_H * 2);             \
    _Pragma("unroll")                                                       \
    for (int it = 0; it < 8; it++) {                                        \
        int idx = it * 128 + tid;                                           \
        int r = idx >> 3, c = idx & 7;                                      \
        cp16(base + (uint32_t)r * (KPAD_H * 2) + (uint32_t)c * 16,          \
             A + (size_t)(m0 + r) * K + _k0 + c * 8);                       \
    }                                                                       \
    _Pragma("unroll")                                                       \
    for (int it = 0; it < 4; it++) {                                        \
        int idx = it * 128 + tid;                                           \
        int r = idx >> 3, c = idx & 7;                                      \
        cp16(base + (STGA64_H * 2) + (uint32_t)r * (KPAD_H * 2)             \
             + (uint32_t)c * 16,                                            \
             Bt + (size_t)(n0 + r) * K + _k0 + c * 8);                      \
    }                                                                       \
    asm volatile("cp.async.commit_group;" ::: "memory");                    \
} while (0)

    LOAD_SLAB64(0);

    for (int i = 0; i < KS; i++) {
        asm volatile("cp.async.wait_group 0;" ::: "memory");   // slab i ready
        __syncthreads();
        if (i + 1 < KS) LOAD_SLAB64(i + 1);

        const __half* As = smh + (i & 1) * STAGE64_H;
        const __half* Bs = As + STGA64_H;

#pragma unroll
        for (int kk = 0; kk < 4; kk++) {
            int kb = kk * 16;
            uint32_t a[4][4], b[4][2];
#pragma unroll
            for (int mi = 0; mi < 4; mi++) {
                int r0 = wm + mi * 16 + gid;
                a[mi][0] = *(const uint32_t*)&As[(r0    ) * KPAD_H + kb + 2 * tig    ];
                a[mi][1] = *(const uint32_t*)&As[(r0 + 8) * KPAD_H + kb + 2 * tig    ];
                a[mi][2] = *(const uint32_t*)&As[(r0    ) * KPAD_H + kb + 2 * tig + 8];
                a[mi][3] = *(const uint32_t*)&As[(r0 + 8) * KPAD_H + kb + 2 * tig + 8];
            }
#pragma unroll
            for (int ni = 0; ni < 4; ni++) {
                int c0 = wn + ni * 8 + gid;
                b[ni][0] = *(const uint32_t*)&Bs[c0 * KPAD_H + kb + 2 * tig    ];
                b[ni][1] = *(const uint32_t*)&Bs[c0 * KPAD_H + kb + 2 * tig + 8];
            }
#pragma unroll
            for (int mi = 0; mi < 4; mi++)
#pragma unroll
                for (int ni = 0; ni < 4; ni++)
                    mma_f16(acc[mi][ni], a[mi], b[ni]);
        }
    }

#pragma unroll
    for (int mi = 0; mi < 4; mi++) {
        int row0 = m0 + wm + mi * 16 + gid;
#pragma unroll
        for (int half_ = 0; half_ < 2; half_++) {
            int row = row0 + half_ * 8;
#pragma unroll
            for (int ni = 0; ni < 4; ni++) {
                int col = n0 + wn + ni * 8 + tig * 2;
                float vx = acc[mi][ni][half_ * 2 + 0];
                float vy = acc[mi][ni][half_ * 2 + 1];
                float2 rr = *(const float2*)&R[(size_t)row * N + col];
                float2 v; v.x = vx + rr.x; v.y = vy + rr.y;
                *(float2*)&C[(size_t)row * N + col] = v;
            }
        }
    }
#undef LOAD_SLAB64
}

// ---------------- MMA flash attention (causal, fp16) ---------------------
__global__ __launch_bounds__(256) void attn_mma(
    const __half* __restrict__ qkv, const __half* __restrict__ vT,
    __half* __restrict__ y)
{
    extern __shared__ __half smh[];
    int tid  = threadIdx.x;
    int wid  = tid >> 5;
    int lane = tid & 31;
    int gid  = lane >> 2;
    int tig  = lane & 3;

    int qt = blockIdx.x;
    int h = blockIdx.y, b = blockIdx.z;
    int q0 = qt * QT;
    int ntiles = 2 * qt + 2;

    const __half* qbase = qkv + (size_t)b * TT * C3 + h * HD;
    const __half* kbase = qkv + (size_t)b * TT * C3 + CEMB + h * HD;
    const __half* vbase = vT + (size_t)(b * NH + h) * HD * TT;

    uint32_t su = smem_u32(smh);

#pragma unroll
    for (int it = 0; it < 4; it++) {
        int idx = it * 256 + tid;
        int r = idx >> 3, c = idx & 7;
        cp16(su + (uint32_t)(r * APAD_H + c * 8) * 2,
             qbase + (size_t)(q0 + r) * C3 + c * 8);
    }

#define LOAD_KV(k0, s) do {                                                  \
    uint32_t kdst = su + (uint32_t)(QS_H + (s) * ASTG_H) * 2;                \
    uint32_t vdst = kdst + KV_H * 2;                                         \
    _Pragma("unroll")                                                        \
    for (int it = 0; it < 2; it++) {                                         \
        int idx = it * 256 + tid;                                            \
        int r = idx >> 3, c = idx & 7;                                       \
        uint32_t off = (uint32_t)(r * APAD_H + c * 8) * 2;                   \
        cp16(kdst + off, kbase + (size_t)((k0) + r) * C3 + c * 8);           \
        cp16(vdst + off, vbase + (size_t)r * TT + (k0) + c * 8);             \
    }                                                                        \
    asm volatile("cp.async.commit_group;" ::: "memory");                     \
} while (0)

    LOAD_KV(0, 0);
    LOAD_KV(KT, 1);

    uint32_t qf[4][4];
    float o[8][4];
#pragma unroll
    for (int ni = 0; ni < 8; ni++)
#pragma unroll
        for (int r = 0; r < 4; r++) o[ni][r] = 0.f;
    float m0v = -INFINITY, m1v = -INFINITY, l0 = 0.f, l1 = 0.f;

    int rw = wid * 16 + gid;
    const __half2 hscale = __float2half2_rn(0.125f);

    for (int i = 0; i < ntiles; i++) {
        if (i < ntiles - 1) {
            asm volatile("cp.async.wait_group 1;" ::: "memory");
        } else {
            asm volatile("cp.async.wait_group 0;" ::: "memory");
        }
        __syncthreads();

        if (i + 2 < ntiles) LOAD_KV((i + 2) * KT, (i + 2) % 3);

        if (i == 0) {
#pragma unroll
            for (int kk = 0; kk < 4; kk++) {
                int kb = kk * 16;
                __half2 h0 = __hmul2(*(const __half2*)&smh[(rw    ) * APAD_H + kb + 2 * tig    ], hscale);
                __half2 h1 = __hmul2(*(const __half2*)&smh[(rw + 8) * APAD_H + kb + 2 * tig    ], hscale);
                __half2 h2 = __hmul2(*(const __half2*)&smh[(rw    ) * APAD_H + kb + 2 * tig + 8], hscale);
                __half2 h3 = __hmul2(*(const __half2*)&smh[(rw + 8) * APAD_H + kb + 2 * tig + 8], hscale);
                qf[kk][0] = *(uint32_t*)&h0; qf[kk][1] = *(uint32_t*)&h1;
                qf[kk][2] = *(uint32_t*)&h2; qf[kk][3] = *(uint32_t*)&h3;
            }
        }

        int k0 = i * KT;
        bool active = (q0 + wid * 16 + 15) >= k0;
        if (active) {
            const __half* Ks = smh + QS_H + (i % 3) * ASTG_H;
            const __half* Vs = Ks + KV_H;

            float sacc[8][4];
#pragma unroll
            for (int ni = 0; ni < 8; ni++)
#pragma unroll
                for (int r = 0; r < 4; r++) sacc[ni][r] = 0.f;

#pragma unroll
            for (int kk = 0; kk < 4; kk++) {
                int kb = kk * 16;
#pragma unroll
                for (int ni = 0; ni < 8; ni++) {
                    uint32_t bb[2];
                    bb[0] = *(const uint32_t*)&Ks[(ni * 8 + gid) * APAD_H + kb + 2 * tig    ];
                    bb[1] = *(const uint32_t*)&Ks[(ni * 8 + gid) * APAD_H + kb + 2 * tig + 8];
                    mma_f16(sacc[ni], qf[kk], bb);
                }
            }

            if (i >= ntiles - 2) {
                int row0 = q0 + rw;
#pragma unroll
                for (int ni = 0; ni < 8; ni++) {
#pragma unroll
                    for (int r = 0; r < 4; r++) {
                        int col = k0 + ni * 8 + 2 * tig + (r & 1);
                        int row = row0 + ((r >= 2) ? 8 : 0);
                        if (col > row) sacc[ni][r] = -INFINITY;
                    }
                }
            }

            float t0 = -INFINITY, t1 = -INFINITY;
#pragma unroll
            for (int ni = 0; ni < 8; ni++) {
                t0 = fmaxf(t0, fmaxf(sacc[ni][0], sacc[ni][1]));
                t1 = fmaxf(t1, fmaxf(sacc[ni][2], sacc[ni][3]));
            }
            t0 = fmaxf(t0, __shfl_xor_sync(0xffffffffu, t0, 1));
            t0 = fmaxf(t0, __shfl_xor_sync(0xffffffffu, t0, 2));
            t1 = fmaxf(t1, __shfl_xor_sync(0xffffffffu, t1, 1));
            t1 = fmaxf(t1, __shfl_xor_sync(0xffffffffu, t1, 2));

            float mn0 = fmaxf(m0v, t0), mn1 = fmaxf(m1v, t1);
            float al0 = exp2f((m0v - mn0) * LOG2E);
            float al1 = exp2f((m1v - mn1) * LOG2E);
            m0v = mn0; m1v = mn1;
            l0 *= al0;  l1 *= al1;
#pragma unroll
            for (int ni = 0; ni < 8; ni++) {
                o[ni][0] *= al0; o[ni][1] *= al0;
                o[ni][2] *= al1; o[ni][3] *= al1;
            }

            uint32_t pf[4][4];
#pragma unroll
            for (int kk = 0; kk < 4; kk++) {
                float p00 = exp2f((sacc[2 * kk    ][0] - mn0) * LOG2E);
                float p01 = exp2f((sacc[2 * kk    ][1] - mn0) * LOG2E);
                float p02 = exp2f((sacc[2 * kk    ][2] - mn1) * LOG2E);
                float p03 = exp2f((sacc[2 * kk    ][3] - mn1) * LOG2E);
                float p10 = exp2f((sacc[2 * kk + 1][0] - mn0) * LOG2E);
                float p11 = exp2f((sacc[2 * kk + 1][1] - mn0) * LOG2E);
                float p12 = exp2f((sacc[2 * kk + 1][2] - mn1) * LOG2E);
                float p13 = exp2f((sacc[2 * kk + 1][3] - mn1) * LOG2E);
                l0 += p00 + p01 + p10 + p11;
                l1 += p02 + p03 + p12 + p13;
                pf[kk][0] = packh2(p00, p01);
                pf[kk][1] = packh2(p02, p03);
                pf[kk][2] = packh2(p10, p11);
                pf[kk][3] = packh2(p12, p13);
            }

#pragma unroll
            for (int kk = 0; kk < 4; kk++) {
                int kb = kk * 16;
#pragma unroll
                for (int ni = 0; ni < 8; ni++) {
                    uint32_t bb[2];
                    bb[0] = *(const uint32_t*)&Vs[(ni * 8 + gid) * APAD_H + kb + 2 * tig    ];
                    bb[1] = *(const uint32_t*)&Vs[(ni * 8 + gid) * APAD_H + kb + 2 * tig + 8];
                    mma_f16(o[ni], pf[kk], bb);
                }
            }
        }
        // no trailing __syncthreads (3-buffer ring)
    }

    l0 += __shfl_xor_sync(0xffffffffu, l0, 1);
    l0 += __shfl_xor_sync(0xffffffffu, l0, 2);
    l1 += __shfl_xor_sync(0xffffffffu, l1, 1);
    l1 += __shfl_xor_sync(0xffffffffu, l1, 2);
    float r0 = 1.0f / l0, r1 = 1.0f / l1;

    int grow0 = (b * TT + q0 + rw);
#pragma unroll
    for (int ni = 0; ni < 8; ni++) {
        int col = h * HD + ni * 8 + 2 * tig;
        *(uint32_t*)&y[(size_t)grow0 * CEMB + col]       = packh2(o[ni][0] * r0, o[ni][1] * r0);
        *(uint32_t*)&y[(size_t)(grow0 + 8) * CEMB + col] = packh2(o[ni][2] * r1, o[ni][3] * r1);
    }
#undef LOAD_KV
}

// ---------------- launch ----------------
extern "C" void kernel_launch(void* const* d_in, const int* in_sizes, int n_in,
                              void* d_out, int out_size)
{
    (void)in_sizes; (void)n_in; (void)out_size;
    const float* x      = (const float*)d_in[0];
    const float* ln1_g  = (const float*)d_in[1];
    const float* ln1_b  = (const float*)d_in[2];
    const float* W_attn = (const float*)d_in[3];
    const float* W_o    = (const float*)d_in[4];
    const float* ln2_g  = (const float*)d_in[5];
    const float* ln2_b  = (const float*)d_in[6];
    const float* W_fc   = (const float*)d_in[7];
    const float* W_proj = (const float*)d_in[8];
    float* out = (float*)d_out;

    __half *p_ln, *p_qkv, *p_vT, *p_att, *p_h;
    __half *p_wattT, *p_woT, *p_wfcT, *p_wprojT;
    float *p_x1;
    cudaGetSymbolAddress((void**)&p_ln,     g_ln);
    cudaGetSymbolAddress((void**)&p_qkv,    g_qkv);
    cudaGetSymbolAddress((void**)&p_vT,     g_vT);
    cudaGetSymbolAddress((void**)&p_att,    g_att);
    cudaGetSymbolAddress((void**)&p_x1,     g_x1);
    cudaGetSymbolAddress((void**)&p_h,      g_h);
    cudaGetSymbolAddress((void**)&p_wattT,  g_wattT);
    cudaGetSymbolAddress((void**)&p_woT,    g_woT);
    cudaGetSymbolAddress((void**)&p_wfcT,   g_wfcT);
    cudaGetSymbolAddress((void**)&p_wprojT, g_wprojT);

    cudaFuncSetAttribute(mma_gemm<2>, cudaFuncAttributeMaxDynamicSharedMemorySize, GEMM_SMEM);
    cudaFuncSetAttribute(mma_gemm<4>, cudaFuncAttributeMaxDynamicSharedMemorySize, GEMM_SMEM);
    cudaFuncSetAttribute(mma_gemm_n64, cudaFuncAttributeMaxDynamicSharedMemorySize, GEMM64_SMEM);
    cudaFuncSetAttribute(attn_mma, cudaFuncAttributeMaxDynamicSharedMemorySize, ATT_SMEM);

    // 0. fused prep: all weight transposes + ln1 in one launch
    prep_kernel<<<PREP_TOTAL, 256>>>(W_attn, W_o, W_fc, W_proj,
                                     p_wattT, p_woT, p_wfcT, p_wprojT,
                                     x, ln1_g, ln1_b, p_ln);

    // 2. qkv = ln1 @ W_attn; Q,K to g_qkv, V staged+transposed to g_vT
    mma_gemm<4><<<dim3(C3 / 128, BT / 128), 256, GEMM_SMEM>>>(
        p_ln, p_wattT, nullptr, p_qkv, p_vT, BT, C3, CEMB);

    // 3. MMA flash attention (half out)
    attn_mma<<<dim3(TT / QT, NH, NB), 256, ATT_SMEM>>>(p_qkv, p_vT, p_att);

    // 4. x1 = att @ W_o + x (float out, n64 v1b)
    mma_gemm_n64<<<dim3(CEMB / 64, BT / 128), 128, GEMM64_SMEM>>>(
        p_att, p_woT, x, p_x1, BT, CEMB, CEMB);

    // 5. ln2
    ln_kernel<<<BT, 256>>>(p_x1, ln2_g, ln2_b, p_ln);

    // 6. h = gelu(ln2 @ W_fc) (half out)
    mma_gemm<2><<<dim3(HID / 128, BT / 128), 256, GEMM_SMEM>>>(
        p_ln, p_wfcT, nullptr, p_h, nullptr, BT, HID, CEMB);

    // 7. out = h @ W_proj + x1 (float out, n64 v1b)
    mma_gemm_n64<<<dim3(CEMB / 64, BT / 128), 128, GEMM64_SMEM>>>(
        p_h, p_wprojT, p_x1, out, BT, CEMB, HID);
}